// round 10
// baseline (speedup 1.0000x reference)
#include <cuda_runtime.h>
#include <math.h>

#define B_    128
#define T_    256
#define NC    128
#define WD    512
#define UNITS 512
#define ZC    2048      // 4*UNITS; gate order i | f | g | o
#define KTOT  1152      // 128 + 512 + 512 (x_char + x_word + h)

// ---- small device-global state (< 1 MB total) ----
__device__ float g_h[2][B_ * UNITS];   // ping-pong hidden, [b][j]
__device__ float g_c[B_ * UNITS];      // cell state, [b][j]
__device__ float g_wsum[ZC];           // 1e-5 * sum of one-hot W rows (t=0 word vec)
__device__ int   g_idx[B_];            // argmax feedback

__device__ __forceinline__ float sigf(float x) { return 1.f / (1.f + expf(-x)); }

// ---- zero initial state ----
__global__ void k_init() {
    int i = blockIdx.x * 256 + threadIdx.x;   // 256 x 256 = 65536
    g_h[0][i] = 0.f;
    g_c[i]    = 0.f;
    if (i < B_) g_idx[i] = 0;
}

// ---- t=0 word vector contribution: 1e-5 * colsum over one-hot rows ----
__global__ void k_wsum(const float* __restrict__ W) {
    int col = blockIdx.x * 256 + threadIdx.x; // 2048
    float s = 0.f;
    for (int r = 0; r < NC; r++)
        s += W[(size_t)(NC + WD + r) * ZC + col];
    g_wsum[col] = 1e-5f * s;
}

// ---- fused step: z = ins@W + h@U + b (+ one-hot row), gates, cell ----
// grid 64 blocks (2 batches each), 256 threads (2 units each).
__global__ void __launch_bounds__(256) k_zstep(
    const float* __restrict__ xc, const float* __restrict__ xw,
    const float* __restrict__ W,  const float* __restrict__ U,
    const float* __restrict__ bias, int t)
{
    const int b0  = blockIdx.x * 2;
    const int tid = threadIdx.x;

    const float* __restrict__ h_in  = g_h[t & 1];
    float* __restrict__       h_out = g_h[(t & 1) ^ 1];

    __shared__ float s_ins[2][KTOT];   // [bi][k]: x_char | x_word | h

    for (int idx = tid; idx < 2 * KTOT; idx += 256) {
        int bi = idx / KTOT, k = idx - bi * KTOT;
        int b = b0 + bi;
        float v;
        if (k < NC)            v = xc[((size_t)b * T_ + t) * NC + k];
        else if (k < NC + WD)  v = xw[((size_t)b * T_ + t) * WD + (k - NC)];
        else                   v = h_in[b * UNITS + (k - NC - WD)];
        s_ins[bi][k] = v;
    }
    __syncthreads();

    float acc[2][4][2];   // [unit-half][gate][batch]
    #pragma unroll
    for (int u = 0; u < 2; u++)
        #pragma unroll
        for (int g = 0; g < 4; g++)
            #pragma unroll
            for (int bi = 0; bi < 2; bi++) acc[u][g][bi] = 0.f;

    for (int k = 0; k < KTOT; k++) {
        const float* wrow = (k < NC + WD) ? (W + (size_t)k * ZC)
                                          : (U + (size_t)(k - NC - WD) * ZC);
        float i0 = s_ins[0][k];
        float i1 = s_ins[1][k];
        #pragma unroll
        for (int u = 0; u < 2; u++) {
            int j = tid + u * 256;
            #pragma unroll
            for (int g = 0; g < 4; g++) {
                float wv = wrow[g * UNITS + j];
                acc[u][g][0] += wv * i0;
                acc[u][g][1] += wv * i1;
            }
        }
    }

    // epilogue: bias + word-vec term, gates, cell update
    int widx0 = g_idx[b0 + 0];
    int widx1 = g_idx[b0 + 1];
    #pragma unroll
    for (int bi = 0; bi < 2; bi++) {
        int b = b0 + bi;
        int widx = bi ? widx1 : widx0;
        const float* wrow = W + (size_t)(NC + WD + widx) * ZC;
        #pragma unroll
        for (int u = 0; u < 2; u++) {
            int j = tid + u * 256;
            float z[4];
            #pragma unroll
            for (int g = 0; g < 4; g++) {
                float extra = (t == 0) ? g_wsum[g * UNITS + j]
                                       : wrow[g * UNITS + j];
                z[g] = acc[u][g][bi] + bias[g * UNITS + j] + extra;
            }
            float ig = sigf(z[0]);
            float fg = sigf(z[1]);
            float gg = tanhf(z[2]);
            float og = sigf(z[3]);
            int ci = b * UNITS + j;
            float cn = fg * g_c[ci] + ig * gg;
            g_c[ci] = cn;
            h_out[ci] = og * tanhf(cn);
        }
    }
}

// ---- logits + argmax (first-index ties, matches jnp.argmax) ----
// OUTPUT IS WRITTEN AS FLOAT32: indices as float values.
__global__ void __launch_bounds__(128) k_out(
    const float* __restrict__ Ws, const float* __restrict__ bs,
    float* __restrict__ out, int t)
{
    const int b = blockIdx.x;
    const int c = threadIdx.x;
    const float* __restrict__ h = g_h[(t & 1) ^ 1];   // h produced by step t

    __shared__ float sh[UNITS];
    for (int i = c; i < UNITS; i += 128) sh[i] = h[b * UNITS + i];
    __syncthreads();

    float s = bs[c];
    for (int j = 0; j < UNITS; j++)
        s += sh[j] * Ws[j * NC + c];

    __shared__ float sv[128];
    __shared__ int   si[128];
    sv[c] = s; si[c] = c;
    __syncthreads();
    #pragma unroll
    for (int off = 64; off > 0; off >>= 1) {
        if (c < off) {
            float ov = sv[c + off]; int oi = si[c + off];
            if (ov > sv[c] || (ov == sv[c] && oi < si[c])) { sv[c] = ov; si[c] = oi; }
        }
        __syncthreads();
    }
    if (c == 0) {
        g_idx[b] = si[0];
        out[b * T_ + t] = (float)si[0];   // float32 output
    }
}

// ---- launch: bind by element count, positional fallback ----
extern "C" void kernel_launch(void* const* d_in, const int* in_sizes, int n_in,
                              void* d_out, int out_size) {
    const float *xc = 0, *xw = 0, *W = 0, *U = 0, *bb = 0, *Ws = 0, *bs = 0;
    for (int i = 0; i < n_in; i++) {
        switch (in_sizes[i]) {
            case 4194304:  xc = (const float*)d_in[i]; break; // 128*256*128
            case 16777216: xw = (const float*)d_in[i]; break; // 128*256*512
            case 1572864:  W  = (const float*)d_in[i]; break; // 768*2048
            case 1048576:  U  = (const float*)d_in[i]; break; // 512*2048
            case 2048:     bb = (const float*)d_in[i]; break;
            case 65536:    Ws = (const float*)d_in[i]; break; // 512*128
            case 128:      bs = (const float*)d_in[i]; break;
            default: break;
        }
    }
    if (!xc || !xw || !W || !U || !bb || !Ws || !bs) {
        xc = (const float*)d_in[0];
        xw = (const float*)d_in[1];
        W  = (const float*)d_in[2];
        U  = (const float*)d_in[3];
        bb = (const float*)d_in[4];
        Ws = (const float*)d_in[5];
        bs = (const float*)d_in[6];
    }
    float* out = (float*)d_out;   // [128, 256] as float32

    k_init<<<256, 256>>>();
    k_wsum<<<8, 256>>>(W);

    for (int t = 0; t < T_; t++) {
        k_zstep<<<64, 256>>>(xc, xw, W, U, bb, t);
        k_out<<<128, 128>>>(Ws, bs, out, t);
    }
}

// round 12
// speedup vs baseline: 5.2626x; 5.2626x over previous
#include <cuda_runtime.h>
#include <math.h>

#define B_    128
#define T_    256
#define NC    128
#define WD    512
#define UNITS 512
#define ZCOLS 2048   // 4*UNITS, Keras gate order: i | f | g | o (512 cols each)

// ---------------- device-global scratch (alloc-free) ----------------
__device__ float g_z0[(size_t)T_ * B_ * ZCOLS]; // [t*128+b][2048] = x@W + b
__device__ float g_h[2][UNITS * B_];            // ping-pong h, layout [unit][batch]
__device__ float g_c[B_ * UNITS];               // c state, layout [batch][unit]
__device__ float g_wsum[ZCOLS];                 // 1e-5 * colsum of one-hot W rows
__device__ float g_plog[16][B_][NC];            // partial logits per 32-unit slice
__device__ int   g_idx[B_];                     // argmax feedback

__device__ __forceinline__ float sigf(float x) { return 1.f / (1.f + expf(-x)); }

// ---------------- zero h0, c0 ----------------
__global__ void k_init() {
    int i = blockIdx.x * 256 + threadIdx.x;   // 256 blocks * 256 = 65536
    g_h[0][i] = 0.f;
    g_c[i]    = 0.f;
    if (i < B_) g_idx[i] = 0;
}

// ---------------- start-word vector: word0 = 1e-5 everywhere ----------------
__global__ void k_wsum(const float* __restrict__ W) {
    int col = blockIdx.x * 256 + threadIdx.x; // 2048
    float s = 0.f;
    for (int cc = 0; cc < NC; cc++)
        s += W[(size_t)(NC + WD + cc) * ZCOLS + col];
    g_wsum[col] = 1e-5f * s;
}

// ---------------- hoisted GEMM: z0[row=t*128+b][col] = x_row @ W[0:640] + b ----
// 64x64 tile, 256 threads, 4 rows x 4 cols per thread, scalar FFMA.
__global__ void __launch_bounds__(256) k_z0(
    const float* __restrict__ xc, const float* __restrict__ xw,
    const float* __restrict__ W,  const float* __restrict__ bias)
{
    const int col0 = blockIdx.x * 64;     // 32 blocks
    const int row0 = blockIdx.y * 64;     // 512 blocks
    const int tid = threadIdx.x;
    const int tc = tid & 15;              // col group (4 cols)
    const int tr = tid >> 4;              // row group (4 rows)

    __shared__ __align__(16) float sx[64][33];  // [row][k]
    __shared__ __align__(16) float sw[32][68];  // [k][col], 272B rows (16-mult)

    float acc[4][4];
    #pragma unroll
    for (int r = 0; r < 4; r++)
        #pragma unroll
        for (int c = 0; c < 4; c++) acc[r][c] = 0.f;

    for (int k0 = 0; k0 < NC + WD; k0 += 32) {
        const bool isChar = (k0 < NC);    // chunks never straddle (128 % 32 == 0)
        #pragma unroll
        for (int r = 0; r < 8; r++) {
            int idx = tid + r * 256;
            int rr = idx >> 5, kk = idx & 31;
            int row = row0 + rr;
            int tt = row >> 7, bb = row & 127;   // row = t*128 + b
            sx[rr][kk] = isChar ? xc[((size_t)bb * T_ + tt) * NC + (k0 + kk)]
                                : xw[((size_t)bb * T_ + tt) * WD + (k0 - NC + kk)];
        }
        #pragma unroll
        for (int r = 0; r < 8; r++) {
            int idx = tid + r * 256;
            int kk = idx >> 6, cc = idx & 63;
            sw[kk][cc] = W[(size_t)(k0 + kk) * ZCOLS + col0 + cc];
        }
        __syncthreads();
        #pragma unroll
        for (int kk = 0; kk < 32; kk++) {
            float4 wq = *(const float4*)&sw[kk][4 * tc];   // 16B-aligned
            #pragma unroll
            for (int r = 0; r < 4; r++) {
                float xv = sx[4 * tr + r][kk];
                acc[r][0] += xv * wq.x;
                acc[r][1] += xv * wq.y;
                acc[r][2] += xv * wq.z;
                acc[r][3] += xv * wq.w;
            }
        }
        __syncthreads();
    }

    const float4 bq = *(const float4*)&bias[col0 + 4 * tc];
    #pragma unroll
    for (int r = 0; r < 4; r++) {
        int row = row0 + 4 * tr + r;
        float4 o;
        o.x = acc[r][0] + bq.x;
        o.y = acc[r][1] + bq.y;
        o.z = acc[r][2] + bq.z;
        o.w = acc[r][3] + bq.w;
        *(float4*)(g_z0 + ((size_t)row << 11) + col0 + 4 * tc) = o;
    }
}

// ---------------- per-step fused: h@U, z assembly, LSTM cell, partial logits --
// grid (16 unit-tiles, 8 batch-tiles), 128 threads.
// Phase 1: thread = (cg: 4 cols of su-layout, bg: 4 batches), 4x4 register tile.
__global__ void __launch_bounds__(128) k_step(
    const float* __restrict__ W, const float* __restrict__ U,
    const float* __restrict__ Ws, int t)
{
    const int jt = blockIdx.x;            // units j0..j0+31
    const int bt = blockIdx.y;            // batches b0..b0+15
    const int j0 = jt * 32, b0 = bt * 16;
    const int tid = threadIdx.x;
    const int cg = tid & 31;              // su cols 4cg..4cg+3
    const int bg = tid >> 5;              // batches 4bg..4bg+3

    const float* __restrict__ h_in  = g_h[t & 1];
    float* __restrict__       h_out = g_h[(t & 1) ^ 1];

    __shared__ __align__(16) float su[32][128]; // [k][gate*32+jl]
    __shared__ __align__(16) float sh[32][16];  // [k][b]
    __shared__ __align__(16) float sz[16][132]; // [b][col], 528B rows (16-mult)
    __shared__ __align__(16) float shv[16][36]; // [b][jl]

    float acc[4][4]; // [ci][bi]
    #pragma unroll
    for (int i = 0; i < 4; i++)
        #pragma unroll
        for (int j = 0; j < 4; j++) acc[i][j] = 0.f;

    for (int k0 = 0; k0 < UNITS; k0 += 32) {
        #pragma unroll
        for (int r = 0; r < 4; r++) {
            int idx = tid + r * 128;
            int kk = idx >> 4, bb = idx & 15;
            sh[kk][bb] = h_in[(k0 + kk) * B_ + b0 + bb];
        }
        #pragma unroll
        for (int r = 0; r < 32; r++) {
            int idx = tid + r * 128;
            int kk = idx >> 7, c = idx & 127;
            su[kk][c] = U[(size_t)(k0 + kk) * ZCOLS + (c >> 5) * UNITS + j0 + (c & 31)];
        }
        __syncthreads();
        #pragma unroll
        for (int kk = 0; kk < 32; kk++) {
            float4 hq = *(const float4*)&sh[kk][4 * bg];
            float4 uq = *(const float4*)&su[kk][4 * cg];
            acc[0][0] += uq.x * hq.x;  acc[0][1] += uq.x * hq.y;
            acc[0][2] += uq.x * hq.z;  acc[0][3] += uq.x * hq.w;
            acc[1][0] += uq.y * hq.x;  acc[1][1] += uq.y * hq.y;
            acc[1][2] += uq.y * hq.z;  acc[1][3] += uq.y * hq.w;
            acc[2][0] += uq.z * hq.x;  acc[2][1] += uq.z * hq.y;
            acc[2][2] += uq.z * hq.z;  acc[2][3] += uq.z * hq.w;
            acc[3][0] += uq.w * hq.x;  acc[3][1] += uq.w * hq.y;
            acc[3][2] += uq.w * hq.z;  acc[3][3] += uq.w * hq.w;
        }
        __syncthreads();
    }

    // z assembly: z = h@U + z0 + word_vec@W, into sz[b][col]
    {
        const int g = cg >> 3;                               // gate of this col quad
        const int zcolb = g * UNITS + j0 + ((4 * cg) & 31);  // global z column base
        #pragma unroll
        for (int bi = 0; bi < 4; bi++) {
            int b = b0 + 4 * bg + bi;
            const float* z0r = g_z0 + ((size_t)(t * B_ + b) << 11) + zcolb;
            float a0, a1, a2, a3;
            if (t == 0) {
                const float* wsr = g_wsum + zcolb;
                a0 = wsr[0]; a1 = wsr[1]; a2 = wsr[2]; a3 = wsr[3];
            } else {
                const float* wr = W + (size_t)(NC + WD + g_idx[b]) * ZCOLS + zcolb;
                a0 = wr[0]; a1 = wr[1]; a2 = wr[2]; a3 = wr[3];
            }
            float4 zq;
            zq.x = acc[0][bi] + z0r[0] + a0;
            zq.y = acc[1][bi] + z0r[1] + a1;
            zq.z = acc[2][bi] + z0r[2] + a2;
            zq.w = acc[3][bi] + z0r[3] + a3;
            *(float4*)&sz[4 * bg + bi][4 * cg] = zq;         // 16B-aligned
        }
    }
    __syncthreads();

    // LSTM cell: thread = (jl, bq), 4 batches each
    {
        const int jl = tid & 31, bq = tid >> 5;
        #pragma unroll
        for (int bi = 0; bi < 4; bi++) {
            int bb = 4 * bq + bi, b = b0 + bb;
            float zi = sz[bb][jl];
            float zf = sz[bb][32 + jl];
            float zg = sz[bb][64 + jl];
            float zo = sz[bb][96 + jl];
            float ig = sigf(zi), fg = sigf(zf);
            float gg = tanhf(zg), og = sigf(zo);
            int ci = b * UNITS + (j0 + jl);
            float cn = fg * g_c[ci] + ig * gg;
            g_c[ci] = cn;
            float hv = og * tanhf(cn);
            h_out[(j0 + jl) * B_ + b] = hv;
            shv[bb][jl] = hv;
        }
    }
    __syncthreads();

    // partial logits: plog[jt][b][c] = sum_jj hv[b][jj] * Ws[j0+jj][c]
    {
        const int c = tid;   // 0..127
        float wv[32];
        #pragma unroll
        for (int jj = 0; jj < 32; jj++) wv[jj] = Ws[(j0 + jj) * NC + c];
        #pragma unroll
        for (int q = 0; q < 16; q++) {
            float ps = 0.f;
            #pragma unroll
            for (int jj = 0; jj < 32; jj++) ps += shv[q][jj] * wv[jj];
            g_plog[jt][b0 + q][c] = ps;
        }
    }
}

// ---------------- reduce + argmax (first-index ties), FLOAT32 output ---------
__global__ void k_argmax(const float* __restrict__ bs, float* __restrict__ out, int t) {
    const int b = blockIdx.x;      // 128
    const int c = threadIdx.x;     // 128
    float s = bs[c];
    #pragma unroll
    for (int q = 0; q < 16; q++) s += g_plog[q][b][c];

    __shared__ float sv[128];
    __shared__ int   si[128];
    sv[c] = s; si[c] = c;
    __syncthreads();
    #pragma unroll
    for (int off = 64; off > 0; off >>= 1) {
        if (c < off) {
            float ov = sv[c + off]; int oi = si[c + off];
            if (ov > sv[c] || (ov == sv[c] && oi < si[c])) { sv[c] = ov; si[c] = oi; }
        }
        __syncthreads();
    }
    if (c == 0) {
        g_idx[b] = si[0];
        out[b * T_ + t] = (float)si[0];   // float32 output (round-10 fix)
    }
}

// ---------------- launch: bind by element count, positional fallback ---------
extern "C" void kernel_launch(void* const* d_in, const int* in_sizes, int n_in,
                              void* d_out, int out_size) {
    const float *xc = 0, *xw = 0, *W = 0, *U = 0, *bb = 0, *Ws = 0, *bs = 0;
    for (int i = 0; i < n_in; i++) {
        switch (in_sizes[i]) {
            case 4194304:  xc = (const float*)d_in[i]; break; // 128*256*128
            case 16777216: xw = (const float*)d_in[i]; break; // 128*256*512
            case 1572864:  W  = (const float*)d_in[i]; break; // 768*2048
            case 1048576:  U  = (const float*)d_in[i]; break; // 512*2048
            case 2048:     bb = (const float*)d_in[i]; break;
            case 65536:    Ws = (const float*)d_in[i]; break; // 512*128
            case 128:      bs = (const float*)d_in[i]; break;
            default: break;
        }
    }
    if (!xc || !xw || !W || !U || !bb || !Ws || !bs) {
        xc = (const float*)d_in[0];
        xw = (const float*)d_in[1];
        W  = (const float*)d_in[2];
        U  = (const float*)d_in[3];
        bb = (const float*)d_in[4];
        Ws = (const float*)d_in[5];
        bs = (const float*)d_in[6];
    }
    float* out = (float*)d_out;   // [128, 256] float32

    k_init<<<256, 256>>>();
    k_wsum<<<8, 256>>>(W);
    k_z0<<<dim3(32, 512), 256>>>(xc, xw, W, bb);

    for (int t = 0; t < T_; t++) {
        k_step<<<dim3(16, 8), 128>>>(W, U, Ws, t);
        k_argmax<<<128, 128>>>(bs, out, t);
    }
}